// round 1
// baseline (speedup 1.0000x reference)
#include <cuda_runtime.h>
#include <math.h>

#define BB 16
#define HH 256
#define WW 256
#define HW (HH*WW)          // 65536
#define NPIX (BB*HW)        // 1048576
#define TPB 256

// Scratch / accumulators (allocation-free: __device__ globals).
// All accumulators are zero at module load and are RESET by the final kernel,
// so every kernel_launch (and every graph replay) starts from zero.
__device__ unsigned char g_pos[NPIX];
__device__ double g_ce;
__device__ double g_inter;
__device__ double g_hard;
__device__ double g_t;
__device__ double g_res[BB];
__device__ int    g_haspos[BB];

// ---------------------------------------------------------------------------
// Kernel A: per-pixel mask + CE + dice counts + has_pos
// inputs layout (B, 2, H, W); targets (B, H, W) int32
// ---------------------------------------------------------------------------
__global__ __launch_bounds__(TPB)
void k_mask_ce_dice(const float* __restrict__ inp, const int* __restrict__ tgt) {
    int idx = blockIdx.x * TPB + threadIdx.x;     // global pixel id
    int b  = idx >> 16;                           // sample (HW = 65536)
    int hw = idx & 65535;

    float x0 = inp[(b * 2    ) * HW + hw];
    float x1 = inp[(b * 2 + 1) * HW + hw];
    int   t  = tgt[idx];

    // CE: -logp[target] with 2-way logsumexp
    float m   = fmaxf(x0, x1);
    float lse = m + log1pf(expf(-fabsf(x1 - x0)));
    float xt  = (t == 1) ? x1 : x0;
    double ce = (double)(lse - xt);

    bool pos  = (x1 >  x0);   // argmax == 1 (ties -> class 0, matches jnp.argmax)
    bool hard = (x1 >= x0);   // p1 >= 0.5
    bool t1   = (t == 1);

    g_pos[idx] = pos ? 1 : 0;

    // dice counts via barrier-count (integer-exact)
    int c_hard  = __syncthreads_count(hard);
    int c_t     = __syncthreads_count(t1);
    int c_inter = __syncthreads_count(hard && t1);
    int any_pos = __syncthreads_or(pos ? 1 : 0);

    // CE block reduce (shared doubles)
    __shared__ double sd[TPB];
    sd[threadIdx.x] = ce;
    __syncthreads();
    #pragma unroll
    for (int s = TPB / 2; s > 0; s >>= 1) {
        if (threadIdx.x < s) sd[threadIdx.x] += sd[threadIdx.x + s];
        __syncthreads();
    }

    if (threadIdx.x == 0) {
        atomicAdd(&g_ce,    sd[0]);
        atomicAdd(&g_hard,  (double)c_hard);
        atomicAdd(&g_t,     (double)c_t);
        atomicAdd(&g_inter, (double)c_inter);
        if (any_pos) g_haspos[b] = 1;   // idempotent store of 1, race-free
    }
}

// ---------------------------------------------------------------------------
// Kernel B: boundary term. At each target==1 pixel, exact Euclidean distance
// to the nearest opposite-class pixel via expanding Chebyshev-ring search.
// Exact: ring r pixels have d2 >= r^2, so stop once r^2 >= best.
// ---------------------------------------------------------------------------
__global__ __launch_bounds__(TPB)
void k_boundary(const int* __restrict__ tgt) {
    int idx = blockIdx.x * TPB + threadIdx.x;
    int b  = idx >> 16;
    int hw = idx & 65535;
    int i  = hw >> 8;     // row
    int j  = hw & 255;    // col

    double contrib = 0.0;
    if (tgt[idx] == 1) {
        const unsigned char* base = g_pos + (b << 16);
        unsigned char myp = base[hw];

        int best = 0x7fffffff;
        for (int r = 1; r < 256; ++r) {
            if (r * r >= best) break;   // cannot improve further
            int y0 = i - r, y1 = i + r;
            int x0 = j - r, x1 = j + r;
            int xs = max(x0, 0), xe = min(x1, 255);
            if (y0 >= 0) {
                int dy2 = r * r;
                const unsigned char* row = base + (y0 << 8);
                for (int x = xs; x <= xe; ++x)
                    if (row[x] != myp) {
                        int dx = x - j; int d2 = dy2 + dx * dx;
                        best = min(best, d2);
                    }
            }
            if (y1 <= 255) {
                int dy2 = r * r;
                const unsigned char* row = base + (y1 << 8);
                for (int x = xs; x <= xe; ++x)
                    if (row[x] != myp) {
                        int dx = x - j; int d2 = dy2 + dx * dx;
                        best = min(best, d2);
                    }
            }
            int ys = max(y0 + 1, 0), ye = min(y1 - 1, 255);
            if (x0 >= 0) {
                int dx2 = r * r;
                for (int y = ys; y <= ye; ++y)
                    if (base[(y << 8) + x0] != myp) {
                        int dy = y - i; int d2 = dx2 + dy * dy;
                        best = min(best, d2);
                    }
            }
            if (x1 <= 255) {
                int dx2 = r * r;
                for (int y = ys; y <= ye; ++y)
                    if (base[(y << 8) + x1] != myp) {
                        int dy = y - i; int d2 = dx2 + dy * dy;
                        best = min(best, d2);
                    }
            }
        }

        float d = (best == 0x7fffffff) ? 1.0e9f : sqrtf((float)best);
        // res = dn*neg - (dp-1)*pos  at this pixel
        contrib = myp ? -(double)(d - 1.0f) : (double)d;
    }

    __shared__ double sd[TPB];
    sd[threadIdx.x] = contrib;
    __syncthreads();
    #pragma unroll
    for (int s = TPB / 2; s > 0; s >>= 1) {
        if (threadIdx.x < s) sd[threadIdx.x] += sd[threadIdx.x + s];
        __syncthreads();
    }
    if (threadIdx.x == 0)
        atomicAdd(&g_res[b], sd[0]);   // whole block lies in one sample (65536 % 256 == 0)
}

// ---------------------------------------------------------------------------
// Kernel C: combine terms, write output, reset accumulators for next replay.
// ---------------------------------------------------------------------------
__global__ void k_final(float* __restrict__ out, int out_size) {
    if (blockIdx.x == 0 && threadIdx.x == 0) {
        double ce = g_ce / (double)NPIX;
        double dice = 1.0 - (2.0 * g_inter + 1.0) / (g_hard + g_t + 1.0);
        double lb = 0.0;
        #pragma unroll
        for (int b = 0; b < BB; ++b) {
            if (g_haspos[b]) lb += g_res[b] / (double)HW;
        }
        double result = ce + dice + lb * lb;
        float r = (float)result;
        for (int k = 0; k < out_size; ++k) out[k] = r;

        // reset for next launch / graph replay
        g_ce = 0.0; g_inter = 0.0; g_hard = 0.0; g_t = 0.0;
        #pragma unroll
        for (int b = 0; b < BB; ++b) { g_res[b] = 0.0; g_haspos[b] = 0; }
    }
}

extern "C" void kernel_launch(void* const* d_in, const int* in_sizes, int n_in,
                              void* d_out, int out_size) {
    const float* inputs  = (const float*)d_in[0];   // (16,2,256,256) f32
    const int*   targets = (const int*)  d_in[1];   // (16,256,256)   i32
    // d_in[2] starget, d_in[3] dice_co, d_in[4] boundary_co: unused by reference math

    const int nblocks = NPIX / TPB;   // 4096
    k_mask_ce_dice<<<nblocks, TPB>>>(inputs, targets);
    k_boundary<<<nblocks, TPB>>>(targets);
    k_final<<<1, 32>>>((float*)d_out, out_size);
}

// round 2
// speedup vs baseline: 1.1327x; 1.1327x over previous
#include <cuda_runtime.h>
#include <math.h>

#define BB 16
#define HW 65536          // 256*256
#define NPIX (BB*HW)      // 1048576
#define TPB 256

// ---- device scratch (allocation-free). Reset by finalize each replay. ----
__device__ unsigned char g_pos[NPIX];
__device__ double g_ce;
__device__ int    g_hard_i, g_t_i, g_inter_i;
__device__ double g_res[BB];
__device__ int    g_haspos[BB];
__device__ unsigned int g_ticket;

// ---------------------------------------------------------------------------
// Kernel A: mask + CE + dice counts. 4 pixels/thread, 2 barriers total.
// ---------------------------------------------------------------------------
__global__ __launch_bounds__(TPB)
void k_prep(const float* __restrict__ inp, const int* __restrict__ tgt) {
    int tid  = threadIdx.x;
    int idx  = (blockIdx.x * TPB + tid) * 4;      // first of 4 pixels
    int b    = idx >> 16;
    int hw   = idx & 65535;

    const float4 x0v = *(const float4*)(inp + (size_t)(b * 2    ) * HW + hw);
    const float4 x1v = *(const float4*)(inp + (size_t)(b * 2 + 1) * HW + hw);
    const int4   tv  = *(const int4*)(tgt + idx);

    float ces = 0.0f;
    int hard = 0, tcnt = 0, inter = 0;
    unsigned char pb[4];

    #define ELEM(K, X0, X1, T) {                                   \
        float x0 = (X0), x1 = (X1); int t = (T);                   \
        float m   = fmaxf(x0, x1);                                 \
        float lse = m + log1pf(__expf(-fabsf(x1 - x0)));           \
        ces += lse - ((t == 1) ? x1 : x0);                         \
        int h  = (x1 >= x0);                                       \
        int t1 = (t == 1);                                         \
        hard += h; tcnt += t1; inter += (h & t1);                  \
        pb[K] = (unsigned char)(x1 > x0); }

    ELEM(0, x0v.x, x1v.x, tv.x)
    ELEM(1, x0v.y, x1v.y, tv.y)
    ELEM(2, x0v.z, x1v.z, tv.z)
    ELEM(3, x0v.w, x1v.w, tv.w)
    #undef ELEM

    *(uchar4*)(g_pos + idx) = make_uchar4(pb[0], pb[1], pb[2], pb[3]);

    // warp reduction
    double ce = (double)ces;
    int p1 = hard | (tcnt << 16);                 // each <= 128/warp, <=1024/block
    int anyp = (pb[0] | pb[1] | pb[2] | pb[3]) ? 1 : 0;
    #pragma unroll
    for (int off = 16; off > 0; off >>= 1) {
        ce    += __shfl_xor_sync(0xffffffffu, ce, off);
        p1    += __shfl_xor_sync(0xffffffffu, p1, off);
        inter += __shfl_xor_sync(0xffffffffu, inter, off);
        anyp  |= __shfl_xor_sync(0xffffffffu, anyp, off);
    }

    __shared__ double s_ce[8];
    __shared__ int    s_p1[8], s_in[8], s_an[8];
    int wid = tid >> 5;
    if ((tid & 31) == 0) { s_ce[wid] = ce; s_p1[wid] = p1; s_in[wid] = inter; s_an[wid] = anyp; }
    __syncthreads();

    if (tid == 0) {
        double bce = 0.0; int bp1 = 0, bin = 0, ban = 0;
        #pragma unroll
        for (int w = 0; w < 8; ++w) { bce += s_ce[w]; bp1 += s_p1[w]; bin += s_in[w]; ban |= s_an[w]; }
        atomicAdd(&g_ce, bce);
        atomicAdd(&g_hard_i,  bp1 & 0xffff);
        atomicAdd(&g_t_i,     bp1 >> 16);
        atomicAdd(&g_inter_i, bin);
        if (ban) g_haspos[b] = 1;                 // block spans 1024 px, single sample
    }
}

// ---------------------------------------------------------------------------
// Kernel B: boundary via exact expanding-row search with uint64 word scans,
// fused finalize in the last-arriving block.
// ---------------------------------------------------------------------------
__device__ __forceinline__ unsigned long long nzmask(unsigned long long v) {
    // high bit of each nonzero byte set
    unsigned long long t = (v & 0x7f7f7f7f7f7f7f7fULL) + 0x7f7f7f7f7f7f7f7fULL;
    return (t | v) & 0x8080808080808080ULL;
}

// min |dx| with row byte[j+dx] != myp (P = splat of myp). Returns big if none
// within the useful bound. Exact for all dx <= dxlim.
__device__ __forceinline__ int row_scan(const unsigned long long* __restrict__ row,
                                        int j, unsigned long long P, int dxlim) {
    int wj = j >> 3, o = j & 7;
    int best = 1 << 20;
    unsigned long long m0 = nzmask(row[wj] ^ P);
    unsigned long long mr = m0 >> (o * 8);
    if (mr) best = (__ffsll((long long)mr) - 1) >> 3;
    unsigned long long ml = m0 << ((7 - o) * 8);
    if (ml) { int d = __clzll((long long)ml) >> 3; best = min(best, d); }

    #pragma unroll 4
    for (int s = 1; s < 32; ++s) {
        int dr0 = 8 * s - o;           // min dx in word wj+s
        int dl0 = 8 * s - 7 + o;       // min dx in word wj-s
        int bound = min(best, dxlim);
        if (dr0 > bound && dl0 > bound) break;
        int wr = wj + s, wl = wj - s;
        if (dr0 <= bound && wr < 32) {
            unsigned long long m = nzmask(row[wr] ^ P);
            if (m) best = min(best, dr0 + ((__ffsll((long long)m) - 1) >> 3));
        }
        bound = min(best, dxlim);
        if (dl0 <= bound && wl >= 0) {
            unsigned long long m = nzmask(row[wl] ^ P);
            if (m) best = min(best, dl0 + (__clzll((long long)m) >> 3));
        }
    }
    return best;
}

__global__ __launch_bounds__(TPB)
void k_boundary(const int* __restrict__ tgt, float* __restrict__ out, int out_size,
                int nblocks) {
    int tid = threadIdx.x;
    int idx = blockIdx.x * TPB + tid;
    int b  = idx >> 16;
    int hw = idx & 65535;
    int i  = hw >> 8;
    int j  = hw & 255;

    double contrib = 0.0;
    if (tgt[idx] == 1) {
        const unsigned char* base = g_pos + (b << 16);
        const unsigned long long* base64 = (const unsigned long long*)base;
        unsigned char myp = base[hw];
        unsigned long long P = myp ? 0x0101010101010101ULL : 0ULL;

        int best2 = 1 << 28;
        for (int dy = 0; dy < 256; ++dy) {
            int dy2 = dy * dy;
            if (dy2 >= best2) break;
            int dxlim = (int)sqrtf((float)(best2 - dy2)) + 1;   // safe over-bound
            if (dxlim > 255) dxlim = 255;
            int yu = i - dy, yd = i + dy;
            if (yu >= 0) {
                int dx = row_scan(base64 + (yu << 5), j, P, dxlim);
                int d2 = dy2 + dx * dx;
                if (dx < (1 << 10) && d2 < best2) best2 = d2;
            }
            if (dy > 0 && yd < 256) {
                int dx = row_scan(base64 + (yd << 5), j, P, dxlim);
                int d2 = dy2 + dx * dx;
                if (dx < (1 << 10) && d2 < best2) best2 = d2;
            }
        }
        float d = (best2 >= (1 << 28)) ? 1.0e9f : sqrtf((float)best2);
        contrib = myp ? -(double)(d - 1.0f) : (double)d;
    }

    // block reduce (warp shuffle + shared stage)
    #pragma unroll
    for (int off = 16; off > 0; off >>= 1)
        contrib += __shfl_xor_sync(0xffffffffu, contrib, off);
    __shared__ double s_c[8];
    int wid = tid >> 5;
    if ((tid & 31) == 0) s_c[wid] = contrib;
    __syncthreads();

    __shared__ bool s_last;
    if (tid == 0) {
        double bc = 0.0;
        #pragma unroll
        for (int w = 0; w < 8; ++w) bc += s_c[w];
        atomicAdd(&g_res[b], bc);          // block spans 256 px, single sample
        __threadfence();
        unsigned int tk = atomicAdd(&g_ticket, 1u);
        s_last = (tk == (unsigned)(nblocks - 1));
    }
    __syncthreads();

    // ---- finalize in the last block ----
    if (s_last && tid == 0) {
        double ce = g_ce / (double)NPIX;
        double hardd = (double)g_hard_i, td = (double)g_t_i, interd = (double)g_inter_i;
        double dice = 1.0 - (2.0 * interd + 1.0) / (hardd + td + 1.0);
        double lb = 0.0;
        #pragma unroll
        for (int s = 0; s < BB; ++s)
            if (g_haspos[s]) lb += g_res[s] / (double)HW;
        float r = (float)(ce + dice + lb * lb);
        for (int k = 0; k < out_size; ++k) out[k] = r;

        // reset all accumulators for next replay
        g_ce = 0.0; g_hard_i = 0; g_t_i = 0; g_inter_i = 0;
        #pragma unroll
        for (int s = 0; s < BB; ++s) { g_res[s] = 0.0; g_haspos[s] = 0; }
        g_ticket = 0u;
    }
}

extern "C" void kernel_launch(void* const* d_in, const int* in_sizes, int n_in,
                              void* d_out, int out_size) {
    const float* inputs  = (const float*)d_in[0];   // (16,2,256,256) f32
    const int*   targets = (const int*)  d_in[1];   // (16,256,256)   i32

    const int blocksA = NPIX / (TPB * 4);   // 1024
    const int blocksB = NPIX / TPB;         // 4096
    k_prep<<<blocksA, TPB>>>(inputs, targets);
    k_boundary<<<blocksB, TPB>>>(targets, (float*)d_out, out_size, blocksB);
}

// round 3
// speedup vs baseline: 2.4726x; 2.1829x over previous
#include <cuda_runtime.h>
#include <math.h>

#define BB 16
#define HW 65536            // 256*256
#define NPIX (BB*HW)        // 1048576
#define WPR 8               // u32 words per row
#define WPS (256*WPR)       // 2048 u32 words per sample
#define NWORDS (BB*WPS)     // 32768

// ---- device scratch (allocation-free). Reset by finalize each replay. ----
__device__ unsigned g_posbits[NWORDS];
__device__ unsigned g_t1bits[NWORDS];
__device__ double g_ce;
__device__ int    g_hard_i, g_t_i, g_inter_i;
__device__ double g_res[BB];
__device__ int    g_haspos[BB];
__device__ int    g_hasneg[BB];
__device__ unsigned int g_ticket;

// ---------------------------------------------------------------------------
// Kernel A: mask/t1 bitboards + CE + dice counts. 4 px/thread.
// ---------------------------------------------------------------------------
__global__ __launch_bounds__(256)
void k_prep(const float* __restrict__ inp, const int* __restrict__ tgt) {
    int tid  = threadIdx.x;
    int idx  = (blockIdx.x * 256 + tid) * 4;
    int b    = idx >> 16;
    int hw   = idx & 65535;

    const float4 x0v = *(const float4*)(inp + (size_t)(b * 2    ) * HW + hw);
    const float4 x1v = *(const float4*)(inp + (size_t)(b * 2 + 1) * HW + hw);
    const int4   tv  = *(const int4*)(tgt + idx);

    float ces = 0.0f;
    int hard = 0, tcnt = 0, inter = 0;
    unsigned pn = 0, tn = 0;   // 4-bit nibbles

    #define ELEM(K, X0, X1, T) {                                   \
        float x0 = (X0), x1 = (X1); int t = (T);                   \
        float m   = fmaxf(x0, x1);                                 \
        float lse = m + log1pf(__expf(-fabsf(x1 - x0)));           \
        ces += lse - ((t == 1) ? x1 : x0);                         \
        int h  = (x1 >= x0);                                       \
        int t1 = (t == 1);                                         \
        hard += h; tcnt += t1; inter += (h & t1);                  \
        pn |= ((unsigned)(x1 > x0)) << (K);                        \
        tn |= ((unsigned)t1) << (K); }

    ELEM(0, x0v.x, x1v.x, tv.x)
    ELEM(1, x0v.y, x1v.y, tv.y)
    ELEM(2, x0v.z, x1v.z, tv.z)
    ELEM(3, x0v.w, x1v.w, tv.w)
    #undef ELEM

    __shared__ unsigned char nib_p[256], nib_t[256];
    nib_p[tid] = (unsigned char)pn;
    nib_t[tid] = (unsigned char)tn;

    // warp reductions for CE / counts / class-presence flags
    double ce = (double)ces;
    int p1 = hard | (tcnt << 16);
    int flags = (pn ? 1 : 0) | ((pn != 0xFu) ? 2 : 0);
    #pragma unroll
    for (int off = 16; off > 0; off >>= 1) {
        ce    += __shfl_xor_sync(0xffffffffu, ce, off);
        p1    += __shfl_xor_sync(0xffffffffu, p1, off);
        inter += __shfl_xor_sync(0xffffffffu, inter, off);
        flags |= __shfl_xor_sync(0xffffffffu, flags, off);
    }

    __shared__ double s_ce[8];
    __shared__ int    s_p1[8], s_in[8], s_fl[8];
    int wid = tid >> 5;
    if ((tid & 31) == 0) { s_ce[wid] = ce; s_p1[wid] = p1; s_in[wid] = inter; s_fl[wid] = flags; }
    __syncthreads();

    // assemble bitboard words: block covers 1024 px = 32 u32 words
    if (tid < 64) {
        int w = tid & 31;                // word within block
        const unsigned char* nb = (tid < 32) ? nib_p : nib_t;
        unsigned v = 0;
        #pragma unroll
        for (int k = 0; k < 8; ++k)
            v |= ((unsigned)nb[8 * w + k]) << (4 * k);
        unsigned* dst = (tid < 32) ? g_posbits : g_t1bits;
        dst[blockIdx.x * 32 + w] = v;
    }

    if (tid == 0) {
        double bce = 0.0; int bp1 = 0, bin = 0, bfl = 0;
        #pragma unroll
        for (int w = 0; w < 8; ++w) { bce += s_ce[w]; bp1 += s_p1[w]; bin += s_in[w]; bfl |= s_fl[w]; }
        atomicAdd(&g_ce, bce);
        atomicAdd(&g_hard_i,  bp1 & 0xffff);
        atomicAdd(&g_t_i,     bp1 >> 16);
        atomicAdd(&g_inter_i, bin);
        if (bfl & 1) g_haspos[b] = 1;    // block spans 1024 px: single sample
        if (bfl & 2) g_hasneg[b] = 1;
    }
}

// ---------------------------------------------------------------------------
// Fallback: exact min |dx| to differing pixel in one row (bitboard scan).
// ---------------------------------------------------------------------------
__device__ __forceinline__ int row_mindx(const unsigned* __restrict__ row, int j, unsigned inv) {
    int wj = j >> 5, off = j & 31;
    int best = 30000;
    unsigned m = (row[wj] ^ inv) >> off;       // own bit cleared (same class)
    if (m) best = __ffs(m) - 1;
    else {
        for (int w = wj + 1; w < WPR; ++w) {
            unsigned x = row[w] ^ inv;
            if (x) { best = 32 * (w - wj) - off + __ffs(x) - 1; break; }
        }
    }
    unsigned ml = (row[wj] ^ inv) << (31 - off);
    if (ml) { int d = __clz(ml); best = min(best, d); }
    else {
        for (int w = wj - 1; w >= 0; --w) {
            unsigned x = row[w] ^ inv;
            if (x) { int d = j - (32 * w + 31 - __clz(x)); best = min(best, d); break; }
        }
    }
    return best;
}

__device__ double fb_contrib(const unsigned* __restrict__ bp, int i, int j, int mybit,
                             int haspos, int hasneg) {
    float d;
    if (!haspos || !hasneg) {
        d = 1.0e9f;                      // reference BIG: no opposite class exists
    } else {
        unsigned inv = mybit ? 0xffffffffu : 0u;
        int best2 = 1 << 30;
        for (int dy = 0; dy < 256; ++dy) {
            int dy2 = dy * dy;
            if (dy2 >= best2) break;
            int up = i - dy, dn = i + dy;
            if (up >= 0) {
                int dx = row_mindx(bp + up * WPR, j, inv);
                int d2 = dy2 + dx * dx;
                if (d2 < best2) best2 = d2;
            }
            if (dy && dn < 256) {
                int dx = row_mindx(bp + dn * WPR, j, inv);
                int d2 = dy2 + dx * dx;
                if (d2 < best2) best2 = d2;
            }
        }
        d = sqrtf((float)best2);
    }
    return mybit ? -(double)(d - 1.0f) : (double)d;
}

// ---------------------------------------------------------------------------
// Kernel B: bit-parallel boundary distances (32 px/thread), fused finalize.
// ---------------------------------------------------------------------------
__global__ __launch_bounds__(256)
void k_boundary(float* __restrict__ out, int out_size, int nblocks) {
    int tw = blockIdx.x * 256 + threadIdx.x;      // word id
    int b  = tw >> 11;                            // 2048 words/sample
    int w  = tw & 2047;
    int i  = w >> 3;                              // row
    int wc = w & 7;                               // word-col

    const unsigned* __restrict__ bp = g_posbits + b * WPS;
    const unsigned* __restrict__ tp = g_t1bits  + b * WPS;

    unsigned lmask = (wc == 0) ? 0xfffffffeu : 0xffffffffu;
    unsigned rmask = (wc == 7) ? 0x7fffffffu : 0xffffffffu;
    unsigned vu = (i > 0)   ? 0xffffffffu : 0u;
    unsigned vd = (i < 255) ? 0xffffffffu : 0u;
    int iu = max(i - 1, 0), id = min(i + 1, 255);

    // own row
    unsigned P  = bp[i * WPR + wc];
    unsigned L0 = (wc > 0) ? bp[i * WPR + wc - 1] : 0u;
    unsigned R0 = (wc < 7) ? bp[i * WPR + wc + 1] : 0u;
    // up row
    unsigned Mu = bp[iu * WPR + wc];
    unsigned Lu = (wc > 0) ? bp[iu * WPR + wc - 1] : 0u;
    unsigned Ru = (wc < 7) ? bp[iu * WPR + wc + 1] : 0u;
    // down row
    unsigned Md = bp[id * WPR + wc];
    unsigned Ld = (wc > 0) ? bp[id * WPR + wc - 1] : 0u;
    unsigned Rd = (wc < 7) ? bp[id * WPR + wc + 1] : 0u;

    unsigned T1 = tp[i * WPR + wc];

    // shifted neighbor values: bit j = pos at (row, col j +/- 1)
    unsigned sm0 = __funnelshift_l(L0, P,  1);   // (0,-1)
    unsigned sp0 = __funnelshift_r(P,  R0, 1);   // (0,+1)
    unsigned smu = __funnelshift_l(Lu, Mu, 1);   // (-1,-1)
    unsigned spu = __funnelshift_r(Mu, Ru, 1);   // (-1,+1)
    unsigned smd = __funnelshift_l(Ld, Md, 1);   // (+1,-1)
    unsigned spd = __funnelshift_r(Md, Rd, 1);   // (+1,+1)

    // d^2 = 1: (0,±1), (±1,0)
    unsigned D1 = ((sm0 ^ P) & lmask) | ((sp0 ^ P) & rmask)
                | ((Mu ^ P) & vu)     | ((Md ^ P) & vd);
    // d^2 = 2: (±1,±1)
    unsigned D2 = ((((smu ^ P) & lmask) | ((spu ^ P) & rmask)) & vu)
                | ((((smd ^ P) & lmask) | ((spd ^ P) & rmask)) & vd);

    unsigned A1 = D1 & T1;
    unsigned A2 = D2 & T1 & ~D1;
    int c1n = __popc(A1 & ~P);                    // neg @ d=1 -> +1 ; pos @ d=1 -> 0
    int c2n = __popc(A2 & ~P);
    int c2p = __popc(A2 & P);

    const double SQ2 = (double)1.41421354f;       // f32 sqrt(2), matches reference math
    double contrib = (double)c1n + (double)c2n * SQ2 - (double)c2p * (SQ2 - 1.0);

    unsigned U = T1 & ~(D1 | D2);                 // rare: no opposite class in 3x3
    if (U) {
        int haspos = g_haspos[b], hasneg = g_hasneg[b];
        do {
            int jb = __ffs(U) - 1; U &= U - 1;
            int j = wc * 32 + jb;
            int mybit = (P >> jb) & 1;
            contrib += fb_contrib(bp, i, j, mybit, haspos, hasneg);
        } while (U);
    }

    // block reduce
    #pragma unroll
    for (int off = 16; off > 0; off >>= 1)
        contrib += __shfl_xor_sync(0xffffffffu, contrib, off);
    __shared__ double s_c[8];
    int wid = threadIdx.x >> 5;
    if ((threadIdx.x & 31) == 0) s_c[wid] = contrib;
    __syncthreads();

    __shared__ bool s_last;
    if (threadIdx.x == 0) {
        double bc = 0.0;
        #pragma unroll
        for (int k = 0; k < 8; ++k) bc += s_c[k];
        atomicAdd(&g_res[b], bc);                 // 2048 % 256 == 0: one sample per block
        __threadfence();
        unsigned int tk = atomicAdd(&g_ticket, 1u);
        s_last = (tk == (unsigned)(nblocks - 1));
    }
    __syncthreads();

    if (s_last && threadIdx.x == 0) {
        double ce = g_ce / (double)NPIX;
        double dice = 1.0 - (2.0 * (double)g_inter_i + 1.0)
                          / ((double)g_hard_i + (double)g_t_i + 1.0);
        double lb = 0.0;
        #pragma unroll
        for (int s = 0; s < BB; ++s)
            if (g_haspos[s]) lb += g_res[s] / (double)HW;
        float r = (float)(ce + dice + lb * lb);
        for (int k = 0; k < out_size; ++k) out[k] = r;

        g_ce = 0.0; g_hard_i = 0; g_t_i = 0; g_inter_i = 0;
        #pragma unroll
        for (int s = 0; s < BB; ++s) { g_res[s] = 0.0; g_haspos[s] = 0; g_hasneg[s] = 0; }
        g_ticket = 0u;
    }
}

extern "C" void kernel_launch(void* const* d_in, const int* in_sizes, int n_in,
                              void* d_out, int out_size) {
    const float* inputs  = (const float*)d_in[0];   // (16,2,256,256) f32
    const int*   targets = (const int*)  d_in[1];   // (16,256,256)   i32

    k_prep<<<NPIX / 1024, 256>>>(inputs, targets);
    const int blocksB = NWORDS / 256;               // 128
    k_boundary<<<blocksB, 256>>>((float*)d_out, out_size, blocksB);
}